// round 14
// baseline (speedup 1.0000x reference)
#include <cuda_runtime.h>
#include <cuda_fp16.h>
#include <cstdint>
#include <cfloat>

#define K_CODES 1024
#define DIM     256
#define T_LEN   4096
#define B_SZ    16
#define N_ROWS  65536
#define QN      ((size_t)16777216)
#define RS      528                     // smem row stride (512B data + 16B pad)
#define TM      64                      // rows per tile
#define NHALF   512                     // codes per CTA (half of K)
#define NCODE   64                      // codes per B chunk
#define NCH     (NHALF / NCODE)         // 8 chunks per CTA
#define NTILES  (N_ROWS / TM)           // 1024
#define A_BYTES (TM * RS)               // 33792
#define B_BYTES (NCODE * RS)            // 33792
#define XTRA    (A_BYTES + 2 * B_BYTES)
#define SMEM_M  (XTRA + 2048)           // 103424 -> 2 CTAs/SM
#define NTHR    256
#define RTHR    256
#define RGRID   128

__device__ __align__(256) __half g_Bh[(size_t)K_CODES * DIM];   // fp16 normalized emb
__device__ __align__(256) float g_enT[DIM * K_CODES];           // fp32 normalized emb^T
__device__ float g_elen[K_CODES];
__device__ float g_e2[K_CODES];
__device__ int   g_rn;
__device__ int   g_rlist[N_ROWS];
__device__ float g_hm1[2 * N_ROWS];
__device__ float g_hm2[2 * N_ROWS];
__device__ int   g_hi1[2 * N_ROWS];
__device__ int   g_done[NTILES];

__device__ __forceinline__ void cp16(uint32_t dst, const void* src) {
    asm volatile("cp.async.cg.shared.global [%0], [%1], 16;\n" :: "r"(dst), "l"(src));
}
__device__ __forceinline__ void cp_commit() { asm volatile("cp.async.commit_group;\n"); }
template <int N> __device__ __forceinline__ void cp_waitg() {
    asm volatile("cp.async.wait_group %0;\n" :: "n"(N));
}
__device__ __forceinline__ void ldsm4(uint32_t* r, uint32_t a) {
    asm volatile("ldmatrix.sync.aligned.m8n8.x4.shared.b16 {%0,%1,%2,%3}, [%4];"
                 : "=r"(r[0]), "=r"(r[1]), "=r"(r[2]), "=r"(r[3]) : "r"(a));
}
__device__ __forceinline__ void ldsm2(uint32_t* r, uint32_t a) {
    asm volatile("ldmatrix.sync.aligned.m8n8.x2.shared.b16 {%0,%1}, [%2];"
                 : "=r"(r[0]), "=r"(r[1]) : "r"(a));
}
__device__ __forceinline__ void mma16816(float* c, const uint32_t* a, const uint32_t* b) {
    asm volatile(
        "mma.sync.aligned.m16n8k16.row.col.f32.f16.f16.f32 "
        "{%0,%1,%2,%3},{%4,%5,%6,%7},{%8,%9},{%0,%1,%2,%3};"
        : "+f"(c[0]), "+f"(c[1]), "+f"(c[2]), "+f"(c[3])
        : "r"(a[0]), "r"(a[1]), "r"(a[2]), "r"(a[3]), "r"(b[0]), "r"(b[1]));
}

// --------- prep B: normalize emb -> g_enT + g_Bh, norms, zero counters -----
__global__ void vq_prepB(const float* __restrict__ emb,
                         float* __restrict__ out, long long out_size) {
    int k = blockIdx.x, d = threadIdx.x;
    float v = emb[(size_t)k * DIM + d];
    float s = v * v;
    #pragma unroll
    for (int o = 16; o; o >>= 1) s += __shfl_xor_sync(0xFFFFFFFFu, s, o);
    __shared__ float ws[8]; __shared__ float rs_sh;
    if ((d & 31) == 0) ws[d >> 5] = s;
    __syncthreads();
    if (d == 0) {
        float t = 0.f;
        #pragma unroll
        for (int i = 0; i < 8; i++) t += ws[i];
        float nrm = sqrtf(t);
        rs_sh = 1.0f / fmaxf(nrm, 1e-12f);
        g_elen[k] = nrm;
        g_e2[k] = t;
        g_done[k] = 0;                    // NTILES == K_CODES == 1024
        if (k == 0) {
            g_rn = 0;
            if (out_size > (long long)QN) out[QN] = 0.0f;
        }
    }
    __syncthreads();
    float en = v * rs_sh;
    g_enT[(size_t)d * K_CODES + k] = en;
    g_Bh[(size_t)k * DIM + d] = __float2half_rn(en);
}

// --------- main: half-tile fp16 mma.sync GEMM + cross-half merge ------------
__global__ void __launch_bounds__(NTHR, 2) vq_main_kernel(
    const float* __restrict__ x, const float* __restrict__ emb,
    float* __restrict__ out, long long out_size)
{
    extern __shared__ char smem[];
    const uint32_t sb = (uint32_t)__cvta_generic_to_shared(smem);
    const uint32_t sbB = sb + A_BYTES;
    const int tid  = threadIdx.x;
    const int lane = tid & 31;
    const int wid  = tid >> 5;
    const int wm   = wid & 1;
    const int wn   = wid >> 1;
    const int tile = blockIdx.x >> 1;
    const int half = blockIdx.x & 1;
    const int n0 = tile * TM;
    const int b  = n0 >> 12;
    const int tl = n0 & 4095;
    const int c0 = half * NHALF;

    float* xn4 = (float*)(smem + XTRA);          // [4][64]
    float* xn2 = (float*)(smem + XTRA + 1024);   // [64] (norm^2)

    auto loadB = [&](int nc) {
        const __half* Bsrc = g_Bh + (size_t)(c0 + nc * NCODE) * DIM;
        uint32_t stg = sbB + (uint32_t)(nc & 1) * B_BYTES;
        #pragma unroll
        for (int i = 0; i < 8; i++) {
            int lin = i * NTHR + tid;
            int row = lin >> 5, q = lin & 31;
            cp16(stg + (uint32_t)(row * RS + q * 16), Bsrc + (size_t)row * DIM + q * 8);
        }
        cp_commit();
    };
    loadB(0); loadB(1);

    // ---- fused prep A: load x tile, fp16 convert into smem, row norms ----
    {
        const int r = tid & 63;
        float ss = 0.f;
        #pragma unroll 8
        for (int i = 0; i < 64; i++) {
            int d = i * 4 + (tid >> 6);
            float v = x[((size_t)b * DIM + d) * T_LEN + tl + r];
            ss = fmaf(v, v, ss);
            *(__half*)(smem + r * RS + d * 2) = __float2half_rn(v);
        }
        xn4[(tid >> 6) * 64 + r] = ss;
    }
    __syncthreads();
    if (tid < TM)
        xn2[tid] = xn4[tid] + xn4[64 + tid] + xn4[128 + tid] + xn4[192 + tid];

    float rm1[4], rm2[4];
    int   ri1[4];
    #pragma unroll
    for (int i = 0; i < 4; i++) { rm1[i] = -FLT_MAX; rm2[i] = -FLT_MAX; ri1[i] = 0; }

    #pragma unroll 1
    for (int nc = 0; nc < NCH; nc++) {
        if (nc < NCH - 2) cp_waitg<1>(); else cp_waitg<0>();
        __syncthreads();

        float acc[2][2][4];
        #pragma unroll
        for (int mt = 0; mt < 2; mt++)
            #pragma unroll
            for (int nt = 0; nt < 2; nt++)
                #pragma unroll
                for (int c = 0; c < 4; c++) acc[mt][nt][c] = 0.f;

        const uint32_t stgB = sbB + (uint32_t)(nc & 1) * B_BYTES;
        #pragma unroll 4
        for (int ks = 0; ks < 16; ks++) {
            uint32_t af[2][4], bf[2][2];
            #pragma unroll
            for (int mt = 0; mt < 2; mt++) {
                int row = wm * 32 + mt * 16 + (lane & 15);
                ldsm4(af[mt], sb + (uint32_t)(row * RS + ks * 32 + (lane >> 4) * 16));
            }
            #pragma unroll
            for (int nt = 0; nt < 2; nt++) {
                int rb = wn * 16 + nt * 8 + (lane & 7);
                ldsm2(bf[nt], stgB + (uint32_t)(rb * RS + ks * 32 + ((lane >> 3) & 1) * 16));
            }
            #pragma unroll
            for (int mt = 0; mt < 2; mt++)
                #pragma unroll
                for (int nt = 0; nt < 2; nt++)
                    mma16816(acc[mt][nt], af[mt], bf[nt]);
        }

        {
            int cb = c0 + nc * NCODE + wn * 16 + 2 * (lane & 3);
            #pragma unroll
            for (int mt = 0; mt < 2; mt++)
                #pragma unroll
                for (int nt = 0; nt < 2; nt++) {
                    int col = cb + nt * 8;
                    #pragma unroll
                    for (int c = 0; c < 4; c++) {
                        int slot = mt * 2 + (c >> 1);
                        int ci = col + (c & 1);
                        float v = acc[mt][nt][c];
                        if (v > rm1[slot]) { rm2[slot] = rm1[slot]; rm1[slot] = v; ri1[slot] = ci; }
                        else if (v > rm2[slot]) rm2[slot] = v;
                    }
                }
        }
        __syncthreads();
        if (nc + 2 < NCH) loadB(nc + 2);
    }
    __syncthreads();

    // ---- cross-partition top-2 reduce (reuse A region as scratch) ----
    float* redm1 = (float*)smem;                 // [64][16]
    int*   redix = (int*)(smem + 4096);
    float* redm2 = (float*)(smem + 8192);
    const int p = wn * 4 + (lane & 3);
    #pragma unroll
    for (int slot = 0; slot < 4; slot++) {
        int row = wm * 32 + (slot >> 1) * 16 + (slot & 1) * 8 + (lane >> 2);
        redm1[row * 16 + p] = rm1[slot];
        redix[row * 16 + p] = ri1[slot];
        redm2[row * 16 + p] = rm2[slot];
    }
    __syncthreads();

    if (tid < TM) {
        float g1 = -FLT_MAX, g2 = -FLT_MAX; int gi = 0;
        #pragma unroll 1
        for (int j = 0; j < 16; j++) {
            float m1 = redm1[tid * 16 + j];
            float m2 = redm2[tid * 16 + j];
            int   ix = redix[tid * 16 + j];
            if (m1 > g1) { g2 = fmaxf(fmaxf(g1, m2), g2); g1 = m1; gi = ix; }
            else         { g2 = fmaxf(g2, m1); }
        }
        int gofs = half * N_ROWS + n0 + tid;
        g_hm1[gofs] = g1;
        g_hm2[gofs] = g2;
        g_hi1[gofs] = gi;
    }
    __syncthreads();

    __shared__ int do_merge;
    if (tid == 0) {
        __threadfence();
        int old = atomicAdd(&g_done[tile], 1);
        do_merge = (old == 1);
        if (do_merge) __threadfence();
    }
    __syncthreads();
    if (!do_merge) return;

    // ---- merge halves, flag, outputs (second-finisher CTA only) ----
    int*   idx_s = (int*)(smem + 12288);         // [64]
    float* bestv = (float*)(smem + 12544);       // [64]
    int*   flg   = (int*)(smem + 12800);         // [64]

    if (tid < TM) {
        float a1 = __ldcg(&g_hm1[n0 + tid]);
        float a2 = __ldcg(&g_hm2[n0 + tid]);
        int   ai = __ldcg(&g_hi1[n0 + tid]);
        float b1 = __ldcg(&g_hm1[N_ROWS + n0 + tid]);
        float b2 = __ldcg(&g_hm2[N_ROWS + n0 + tid]);
        int   bi = __ldcg(&g_hi1[N_ROWS + n0 + tid]);
        float g1, g2; int gi;
        if (a1 > b1)      { g1 = a1; gi = ai; g2 = fmaxf(a2, b1); }
        else if (b1 > a1) { g1 = b1; gi = bi; g2 = fmaxf(b2, a1); }
        else              { g1 = a1; gi = ai < bi ? ai : bi; g2 = a1; }   // tie -> flag
        idx_s[tid] = gi;
        bestv[tid] = g1;
        int f = (g1 - g2 < 2e-4f * sqrtf(xn2[tid])) ? 1 : 0;
        flg[tid] = f;
        if (f) {
            int q = atomicAdd(&g_rn, 1);
            g_rlist[q] = n0 + tid;
        }
    }
    __syncthreads();

    if (tid < TM && !flg[tid] && out_size >= (long long)(QN + 1 + N_ROWS))
        out[QN + 1 + n0 + tid] = (float)idx_s[tid];

    if (tid < TM) {
        float lr = 0.f;
        if (!flg[tid]) {
            int gi = idx_s[tid];
            lr = xn2[tid] - 2.0f * g_elen[gi] * bestv[tid] + g_e2[gi];
        }
        redm1[tid] = lr;
    }
    __syncthreads();
    if (tid == 0 && out_size > (long long)QN) {
        float t = 0.f;
        #pragma unroll 1
        for (int j = 0; j < TM; j++) t += redm1[j];
        atomicAdd(out + QN, t * (1.25f / 16777216.0f));
    }

    const int r  = tid & 63;
    const int dq = tid >> 6;
    if (!flg[r]) {
        const int myidx = idx_s[r];
        const float4* erow4 = (const float4*)(emb + (size_t)myidx * DIM + dq * 64);
        float* ob = out + ((size_t)b * DIM + dq * 64) * T_LEN + tl + r;
        #pragma unroll 4
        for (int dj = 0; dj < 16; ++dj) {
            float4 e4 = erow4[dj];
            int d = dj * 4;
            ob[(size_t)(d + 0) * T_LEN] = e4.x;
            ob[(size_t)(d + 1) * T_LEN] = e4.y;
            ob[(size_t)(d + 2) * T_LEN] = e4.z;
            ob[(size_t)(d + 3) * T_LEN] = e4.w;
        }
    }
}

// --------- rescue: exact fp32 argmax + outputs for flagged rows -------------
__global__ void __launch_bounds__(RTHR, 2) vq_rescue(
    const float* __restrict__ x, const float* __restrict__ emb,
    float* __restrict__ out, long long out_size)
{
    __shared__ float xs8[8 * 256];
    __shared__ float xn8[8];
    __shared__ float rwv[8 * 8];
    __shared__ int   rwi[8 * 8];
    __shared__ int   bsel[8];
    const int tid = threadIdx.x, lane = tid & 31, wid = tid >> 5;
    const int total = g_rn;

    #pragma unroll 1
    for (int base = blockIdx.x * 8; base < total; base += gridDim.x * 8) {
        const int nb = min(8, total - base);
        #pragma unroll
        for (int i = 0; i < 8; i++) {
            int lin = i * RTHR + tid;
            int r = lin >> 8, d = lin & 255;
            int nn = g_rlist[base + (r < nb ? r : 0)];
            xs8[r * 256 + d] = x[((size_t)(nn >> 12) * DIM + d) * T_LEN + (nn & 4095)];
        }
        __syncthreads();
        {
            float s = 0.f;
            #pragma unroll
            for (int j = 0; j < 8; j++) {
                float v = xs8[wid * 256 + lane + 32 * j];
                s = fmaf(v, v, s);
            }
            #pragma unroll
            for (int o = 16; o; o >>= 1) s += __shfl_xor_sync(0xFFFFFFFFu, s, o);
            if (lane == 0) xn8[wid] = s;
        }
        float a0[8], a1[8], a2[8], a3[8];
        #pragma unroll
        for (int r = 0; r < 8; r++) { a0[r] = 0.f; a1[r] = 0.f; a2[r] = 0.f; a3[r] = 0.f; }
        #pragma unroll 4
        for (int d = 0; d < 256; d++) {
            const float* ed = g_enT + d * K_CODES + tid;
            float e0 = ed[0], e1 = ed[256], e2v = ed[512], e3 = ed[768];
            #pragma unroll
            for (int r = 0; r < 8; r++) {
                float xv = xs8[r * 256 + d];
                a0[r] = fmaf(xv, e0, a0[r]);
                a1[r] = fmaf(xv, e1, a1[r]);
                a2[r] = fmaf(xv, e2v, a2[r]);
                a3[r] = fmaf(xv, e3, a3[r]);
            }
        }
        #pragma unroll 1
        for (int r = 0; r < nb; r++) {
            float bv = a0[r]; int bi = tid;
            if (a1[r] > bv) { bv = a1[r]; bi = tid + 256; }
            if (a2[r] > bv) { bv = a2[r]; bi = tid + 512; }
            if (a3[r] > bv) { bv = a3[r]; bi = tid + 768; }
            #pragma unroll
            for (int o = 16; o; o >>= 1) {
                float ov = __shfl_xor_sync(0xFFFFFFFFu, bv, o);
                int   oi = __shfl_xor_sync(0xFFFFFFFFu, bi, o);
                if (ov > bv || (ov == bv && oi < bi)) { bv = ov; bi = oi; }
            }
            if (lane == 0) { rwv[r * 8 + wid] = bv; rwi[r * 8 + wid] = bi; }
        }
        __syncthreads();
        if (tid < nb) {
            float best = rwv[tid * 8]; int besti = rwi[tid * 8];
            #pragma unroll
            for (int j = 1; j < 8; j++) {
                float v = rwv[tid * 8 + j]; int ix = rwi[tid * 8 + j];
                if (v > best || (v == best && ix < besti)) { best = v; besti = ix; }
            }
            bsel[tid] = besti;
            int nn = g_rlist[base + tid];
            if (out_size >= (long long)(QN + 1 + N_ROWS))
                out[QN + 1 + nn] = (float)besti;
            if (out_size > (long long)QN)
                atomicAdd(out + QN,
                    (xn8[tid] - 2.0f * g_elen[besti] * best + g_e2[besti]) * (1.25f / 16777216.0f));
        }
        __syncthreads();
        #pragma unroll 1
        for (int r = 0; r < nb; r++) {
            int nn = g_rlist[base + r];
            int bi = bsel[r];
            out[((size_t)(nn >> 12) * DIM + tid) * T_LEN + (nn & 4095)] =
                emb[(size_t)bi * DIM + tid];
        }
        __syncthreads();
    }
}

// ---------------------------------------------------------------------------
extern "C" void kernel_launch(void* const* d_in, const int* in_sizes, int n_in,
                              void* d_out, int out_size) {
    const float* x   = (const float*)d_in[0];
    const float* emb = (const float*)d_in[1];
    if (n_in >= 2 && in_sizes[0] == K_CODES * DIM && in_sizes[1] == (int)QN) {
        const float* t = x; x = emb; emb = t;
    }
    float* out = (float*)d_out;

    cudaFuncSetAttribute(vq_main_kernel, cudaFuncAttributeMaxDynamicSharedMemorySize, SMEM_M);

    vq_prepB<<<K_CODES, 256>>>(emb, out, (long long)out_size);
    vq_main_kernel<<<NTILES * 2, NTHR, SMEM_M>>>(x, emb, out, (long long)out_size);
    vq_rescue<<<RGRID, RTHR>>>(x, emb, out, (long long)out_size);
}

// round 15
// speedup vs baseline: 1.0683x; 1.0683x over previous
#include <cuda_runtime.h>
#include <cuda_fp16.h>
#include <cstdint>
#include <cfloat>

#define K_CODES 1024
#define DIM     256
#define T_LEN   4096
#define B_SZ    16
#define N_ROWS  65536
#define QN      ((size_t)16777216)
#define RS      528                     // smem row stride (512B data + 16B pad)
#define TM      64                      // rows per CTA
#define NCODE   64                      // codes per B chunk
#define NCH     (K_CODES / NCODE)       // 16 chunks
#define A_BYTES (TM * RS)               // 33792
#define B_BYTES (NCODE * RS)            // 33792
#define XTRA    (A_BYTES + 2 * B_BYTES)
#define SMEM_M  (XTRA + 2048)           // 103424 -> 2 CTAs/SM
#define NTHR    256
#define RTHR    256
#define RGRID   128

__device__ __align__(256) __half g_Bh[(size_t)K_CODES * DIM];   // fp16 normalized emb
__device__ __align__(256) float g_enT[DIM * K_CODES];           // fp32 normalized emb^T
__device__ float g_elen[K_CODES];
__device__ float g_e2[K_CODES];
__device__ int   g_rn;
__device__ int   g_rlist[N_ROWS];

__device__ __forceinline__ void cp16(uint32_t dst, const void* src) {
    asm volatile("cp.async.cg.shared.global [%0], [%1], 16;\n" :: "r"(dst), "l"(src));
}
__device__ __forceinline__ void cp_commit() { asm volatile("cp.async.commit_group;\n"); }
template <int N> __device__ __forceinline__ void cp_waitg() {
    asm volatile("cp.async.wait_group %0;\n" :: "n"(N));
}
__device__ __forceinline__ void ldsm4(uint32_t* r, uint32_t a) {
    asm volatile("ldmatrix.sync.aligned.m8n8.x4.shared.b16 {%0,%1,%2,%3}, [%4];"
                 : "=r"(r[0]), "=r"(r[1]), "=r"(r[2]), "=r"(r[3]) : "r"(a));
}
__device__ __forceinline__ void mma16816(float* c, const uint32_t* a, const uint32_t* b) {
    asm volatile(
        "mma.sync.aligned.m16n8k16.row.col.f32.f16.f16.f32 "
        "{%0,%1,%2,%3},{%4,%5,%6,%7},{%8,%9},{%0,%1,%2,%3};"
        : "+f"(c[0]), "+f"(c[1]), "+f"(c[2]), "+f"(c[3])
        : "r"(a[0]), "r"(a[1]), "r"(a[2]), "r"(a[3]), "r"(b[0]), "r"(b[1]));
}

// --------- prep B: normalize emb -> g_enT + g_Bh, norms, zero counters -----
__global__ void vq_prepB(const float* __restrict__ emb,
                         float* __restrict__ out, long long out_size) {
    int k = blockIdx.x, d = threadIdx.x;
    float v = emb[(size_t)k * DIM + d];
    float s = v * v;
    #pragma unroll
    for (int o = 16; o; o >>= 1) s += __shfl_xor_sync(0xFFFFFFFFu, s, o);
    __shared__ float ws[8]; __shared__ float rs_sh;
    if ((d & 31) == 0) ws[d >> 5] = s;
    __syncthreads();
    if (d == 0) {
        float t = 0.f;
        #pragma unroll
        for (int i = 0; i < 8; i++) t += ws[i];
        float nrm = sqrtf(t);
        rs_sh = 1.0f / fmaxf(nrm, 1e-12f);
        g_elen[k] = nrm;
        g_e2[k] = t;
        if (k == 0) {
            g_rn = 0;
            if (out_size > (long long)QN) out[QN] = 0.0f;
        }
    }
    __syncthreads();
    float en = v * rs_sh;
    g_enT[(size_t)d * K_CODES + k] = en;
    g_Bh[(size_t)k * DIM + d] = __float2half_rn(en);
}

// --------- main: fused prologue + fp16 mma.sync GEMM + argmax + epilogue ----
__global__ void __launch_bounds__(NTHR, 2) vq_main_kernel(
    const float* __restrict__ x, const float* __restrict__ emb,
    float* __restrict__ out, long long out_size)
{
    extern __shared__ char smem[];
    const uint32_t sb = (uint32_t)__cvta_generic_to_shared(smem);
    const uint32_t sbB = sb + A_BYTES;
    const int tid  = threadIdx.x;
    const int lane = tid & 31;
    const int wid  = tid >> 5;
    const int wm   = wid & 1;
    const int wn   = wid >> 1;
    const int n0 = blockIdx.x * TM;
    const int b  = n0 >> 12;
    const int tl = n0 & 4095;

    float* xn4 = (float*)(smem + XTRA);          // [4][64]
    float* xn2 = (float*)(smem + XTRA + 1024);   // [64] (norm^2)

    auto loadB = [&](int nc) {
        const __half* Bsrc = g_Bh + (size_t)(nc * NCODE) * DIM;
        uint32_t stg = sbB + (uint32_t)(nc & 1) * B_BYTES;
        #pragma unroll
        for (int i = 0; i < 8; i++) {
            int lin = i * NTHR + tid;
            int row = lin >> 5, q = lin & 31;
            cp16(stg + (uint32_t)(row * RS + q * 16), Bsrc + (size_t)row * DIM + q * 8);
        }
        cp_commit();
    };
    loadB(0); loadB(1);

    // ---- fused prep A: load x tile, fp16 convert into smem, row norms ----
    {
        const int r = tid & 63;
        float ss = 0.f;
        #pragma unroll 8
        for (int i = 0; i < 64; i++) {
            int d = i * 4 + (tid >> 6);
            float v = x[((size_t)b * DIM + d) * T_LEN + tl + r];
            ss = fmaf(v, v, ss);
            *(__half*)(smem + r * RS + d * 2) = __float2half_rn(v);
        }
        xn4[(tid >> 6) * 64 + r] = ss;
    }
    __syncthreads();
    if (tid < TM)
        xn2[tid] = xn4[tid] + xn4[64 + tid] + xn4[128 + tid] + xn4[192 + tid];

    float rm1[4], rm2[4];
    int   ri1[4];
    #pragma unroll
    for (int i = 0; i < 4; i++) { rm1[i] = -FLT_MAX; rm2[i] = -FLT_MAX; ri1[i] = 0; }

    // B ldsm4 lane mapping (2 nt tiles in one ldmatrix):
    // lanes 0-15 -> rows wn*16 + (lane&7) [nt0], lanes 16-31 -> +8 [nt1];
    // k-half per 8-lane group: lanes 0-7 klo, 8-15 khi, 16-23 klo, 24-31 khi.
    const int brow = wn * 16 + ((lane >> 4) << 3) + (lane & 7);
    const uint32_t bko = (uint32_t)(((lane >> 3) & 1) * 16);

    #pragma unroll 1
    for (int nc = 0; nc < NCH; nc++) {
        if (nc < NCH - 2) cp_waitg<1>(); else cp_waitg<0>();
        __syncthreads();                          // A(STS) + B-chunk nc resident

        float acc[2][2][4];
        #pragma unroll
        for (int mt = 0; mt < 2; mt++)
            #pragma unroll
            for (int nt = 0; nt < 2; nt++)
                #pragma unroll
                for (int c = 0; c < 4; c++) acc[mt][nt][c] = 0.f;

        const uint32_t stgB = sbB + (uint32_t)(nc & 1) * B_BYTES;
        #pragma unroll 4
        for (int ks = 0; ks < 16; ks++) {
            uint32_t af[2][4], bq[4];
            #pragma unroll
            for (int mt = 0; mt < 2; mt++) {
                int row = wm * 32 + mt * 16 + (lane & 15);
                ldsm4(af[mt], sb + (uint32_t)(row * RS + ks * 32 + (lane >> 4) * 16));
            }
            ldsm4(bq, stgB + (uint32_t)(brow * RS + ks * 32) + bko);
            #pragma unroll
            for (int mt = 0; mt < 2; mt++) {
                mma16816(acc[mt][0], af[mt], bq);      // bq[0],bq[1] = nt0
                mma16816(acc[mt][1], af[mt], bq + 2);  // bq[2],bq[3] = nt1
            }
        }

        {
            int cb = nc * NCODE + wn * 16 + 2 * (lane & 3);
            #pragma unroll
            for (int mt = 0; mt < 2; mt++)
                #pragma unroll
                for (int nt = 0; nt < 2; nt++) {
                    int col = cb + nt * 8;
                    #pragma unroll
                    for (int c = 0; c < 4; c++) {
                        int slot = mt * 2 + (c >> 1);
                        int ci = col + (c & 1);
                        float v = acc[mt][nt][c];
                        if (v > rm1[slot]) { rm2[slot] = rm1[slot]; rm1[slot] = v; ri1[slot] = ci; }
                        else if (v > rm2[slot]) rm2[slot] = v;
                    }
                }
        }
        __syncthreads();
        if (nc + 2 < NCH) loadB(nc + 2);
    }
    __syncthreads();

    // ---- cross-partition top-2 reduce (reuse A region as scratch) ----
    float* redm1 = (float*)smem;                 // [64][16]
    int*   redix = (int*)(smem + 4096);          // [64][16]
    float* redm2 = (float*)(smem + 8192);        // [64][16]
    const int p = wn * 4 + (lane & 3);
    #pragma unroll
    for (int slot = 0; slot < 4; slot++) {
        int row = wm * 32 + (slot >> 1) * 16 + (slot & 1) * 8 + (lane >> 2);
        redm1[row * 16 + p] = rm1[slot];
        redix[row * 16 + p] = ri1[slot];
        redm2[row * 16 + p] = rm2[slot];
    }
    __syncthreads();

    int*   idx_s = (int*)(smem + 12288);         // [64]
    float* bestv = (float*)(smem + 12544);       // [64]
    int*   flg   = (int*)(smem + 12800);         // [64]

    if (tid < TM) {
        float g1 = -FLT_MAX, g2 = -FLT_MAX; int gi = 0;
        #pragma unroll 1
        for (int j = 0; j < 16; j++) {
            float m1 = redm1[tid * 16 + j];
            float m2 = redm2[tid * 16 + j];
            int   ix = redix[tid * 16 + j];
            if (m1 > g1) { g2 = fmaxf(fmaxf(g1, m2), g2); g1 = m1; gi = ix; }
            else         { g2 = fmaxf(g2, m1); }
        }
        idx_s[tid] = gi;
        bestv[tid] = g1;
        int f = (g1 - g2 < 2e-4f * sqrtf(xn2[tid])) ? 1 : 0;  // fp16-dot 10+ sigma
        flg[tid] = f;
        if (f) {
            int q = atomicAdd(&g_rn, 1);
            g_rlist[q] = n0 + tid;
        }
    }
    __syncthreads();

    if (tid < TM && !flg[tid] && out_size >= (long long)(QN + 1 + N_ROWS))
        out[QN + 1 + n0 + tid] = (float)idx_s[tid];

    // ---- loss from norms (per-row, non-flagged) ----
    if (tid < TM) {
        float lr = 0.f;
        if (!flg[tid]) {
            int gi = idx_s[tid];
            lr = xn2[tid] - 2.0f * g_elen[gi] * bestv[tid] + g_e2[gi];
        }
        redm1[tid] = lr;
    }
    __syncthreads();
    if (tid == 0 && out_size > (long long)QN) {
        float t = 0.f;
        #pragma unroll 1
        for (int j = 0; j < TM; j++) t += redm1[j];
        atomicAdd(out + QN, t * (1.25f / 16777216.0f));
    }

    // ---- gather + quantized write (non-flagged rows) ----
    const int r  = tid & 63;
    const int dq = tid >> 6;
    if (!flg[r]) {
        const int myidx = idx_s[r];
        const float4* erow4 = (const float4*)(emb + (size_t)myidx * DIM + dq * 64);
        float* ob = out + ((size_t)b * DIM + dq * 64) * T_LEN + tl + r;
        #pragma unroll 4
        for (int dj = 0; dj < 16; ++dj) {
            float4 e4 = erow4[dj];
            int d = dj * 4;
            ob[(size_t)(d + 0) * T_LEN] = e4.x;
            ob[(size_t)(d + 1) * T_LEN] = e4.y;
            ob[(size_t)(d + 2) * T_LEN] = e4.z;
            ob[(size_t)(d + 3) * T_LEN] = e4.w;
        }
    }
}

// --------- rescue: exact fp32 argmax + outputs for flagged rows -------------
__global__ void __launch_bounds__(RTHR, 2) vq_rescue(
    const float* __restrict__ x, const float* __restrict__ emb,
    float* __restrict__ out, long long out_size)
{
    __shared__ float xs8[8 * 256];
    __shared__ float xn8[8];
    __shared__ float rwv[8 * 8];
    __shared__ int   rwi[8 * 8];
    __shared__ int   bsel[8];
    const int tid = threadIdx.x, lane = tid & 31, wid = tid >> 5;
    const int total = g_rn;

    #pragma unroll 1
    for (int base = blockIdx.x * 8; base < total; base += gridDim.x * 8) {
        const int nb = min(8, total - base);
        #pragma unroll
        for (int i = 0; i < 8; i++) {
            int lin = i * RTHR + tid;
            int r = lin >> 8, d = lin & 255;
            int nn = g_rlist[base + (r < nb ? r : 0)];
            xs8[r * 256 + d] = x[((size_t)(nn >> 12) * DIM + d) * T_LEN + (nn & 4095)];
        }
        __syncthreads();
        {
            float s = 0.f;
            #pragma unroll
            for (int j = 0; j < 8; j++) {
                float v = xs8[wid * 256 + lane + 32 * j];
                s = fmaf(v, v, s);
            }
            #pragma unroll
            for (int o = 16; o; o >>= 1) s += __shfl_xor_sync(0xFFFFFFFFu, s, o);
            if (lane == 0) xn8[wid] = s;
        }
        float a0[8], a1[8], a2[8], a3[8];
        #pragma unroll
        for (int r = 0; r < 8; r++) { a0[r] = 0.f; a1[r] = 0.f; a2[r] = 0.f; a3[r] = 0.f; }
        #pragma unroll 4
        for (int d = 0; d < 256; d++) {
            const float* ed = g_enT + d * K_CODES + tid;
            float e0 = ed[0], e1 = ed[256], e2v = ed[512], e3 = ed[768];
            #pragma unroll
            for (int r = 0; r < 8; r++) {
                float xv = xs8[r * 256 + d];
                a0[r] = fmaf(xv, e0, a0[r]);
                a1[r] = fmaf(xv, e1, a1[r]);
                a2[r] = fmaf(xv, e2v, a2[r]);
                a3[r] = fmaf(xv, e3, a3[r]);
            }
        }
        #pragma unroll 1
        for (int r = 0; r < nb; r++) {
            float bv = a0[r]; int bi = tid;
            if (a1[r] > bv) { bv = a1[r]; bi = tid + 256; }
            if (a2[r] > bv) { bv = a2[r]; bi = tid + 512; }
            if (a3[r] > bv) { bv = a3[r]; bi = tid + 768; }
            #pragma unroll
            for (int o = 16; o; o >>= 1) {
                float ov = __shfl_xor_sync(0xFFFFFFFFu, bv, o);
                int   oi = __shfl_xor_sync(0xFFFFFFFFu, bi, o);
                if (ov > bv || (ov == bv && oi < bi)) { bv = ov; bi = oi; }
            }
            if (lane == 0) { rwv[r * 8 + wid] = bv; rwi[r * 8 + wid] = bi; }
        }
        __syncthreads();
        if (tid < nb) {
            float best = rwv[tid * 8]; int besti = rwi[tid * 8];
            #pragma unroll
            for (int j = 1; j < 8; j++) {
                float v = rwv[tid * 8 + j]; int ix = rwi[tid * 8 + j];
                if (v > best || (v == best && ix < besti)) { best = v; besti = ix; }
            }
            bsel[tid] = besti;
            int nn = g_rlist[base + tid];
            if (out_size >= (long long)(QN + 1 + N_ROWS))
                out[QN + 1 + nn] = (float)besti;
            if (out_size > (long long)QN)
                atomicAdd(out + QN,
                    (xn8[tid] - 2.0f * g_elen[besti] * best + g_e2[besti]) * (1.25f / 16777216.0f));
        }
        __syncthreads();
        #pragma unroll 1
        for (int r = 0; r < nb; r++) {
            int nn = g_rlist[base + r];
            int bi = bsel[r];
            out[((size_t)(nn >> 12) * DIM + tid) * T_LEN + (nn & 4095)] =
                emb[(size_t)bi * DIM + tid];
        }
        __syncthreads();
    }
}

// ---------------------------------------------------------------------------
extern "C" void kernel_launch(void* const* d_in, const int* in_sizes, int n_in,
                              void* d_out, int out_size) {
    const float* x   = (const float*)d_in[0];
    const float* emb = (const float*)d_in[1];
    if (n_in >= 2 && in_sizes[0] == K_CODES * DIM && in_sizes[1] == (int)QN) {
        const float* t = x; x = emb; emb = t;
    }
    float* out = (float*)d_out;

    cudaFuncSetAttribute(vq_main_kernel, cudaFuncAttributeMaxDynamicSharedMemorySize, SMEM_M);

    vq_prepB<<<K_CODES, 256>>>(emb, out, (long long)out_size);
    vq_main_kernel<<<N_ROWS / TM, NTHR, SMEM_M>>>(x, emb, out, (long long)out_size);
    vq_rescue<<<RGRID, RTHR>>>(x, emb, out, (long long)out_size);
}

// round 16
// speedup vs baseline: 1.1848x; 1.1090x over previous
#include <cuda_runtime.h>
#include <cuda_fp16.h>
#include <cstdint>
#include <cfloat>

#define K_CODES 1024
#define DIM     256
#define T_LEN   4096
#define B_SZ    16
#define N_ROWS  65536
#define QN      ((size_t)16777216)
#define RS      528                     // smem row stride (512B data + 16B pad)
#define TM      64                      // rows per CTA
#define NCODE   64                      // codes per B chunk
#define NCH     (K_CODES / NCODE)       // 16 chunks
#define A_BYTES (TM * RS)               // 33792
#define B_BYTES (NCODE * RS)            // 33792
#define XTRA    (A_BYTES + 2 * B_BYTES)
#define SMEM_M  (XTRA + 2048)           // 103424 -> 2 CTAs/SM
#define NTHR    256
#define RTHR    256
#define RGRID   128

__device__ __align__(256) __half g_Bh[(size_t)K_CODES * DIM];   // fp16 normalized emb
__device__ __align__(256) float g_enT[DIM * K_CODES];           // fp32 normalized emb^T
__device__ float g_elen[K_CODES];
__device__ float g_e2[K_CODES];
__device__ int   g_rn;
__device__ int   g_rlist[N_ROWS];

__device__ __forceinline__ void cp16(uint32_t dst, const void* src) {
    asm volatile("cp.async.cg.shared.global [%0], [%1], 16;\n" :: "r"(dst), "l"(src));
}
__device__ __forceinline__ void cp_commit() { asm volatile("cp.async.commit_group;\n"); }
template <int N> __device__ __forceinline__ void cp_waitg() {
    asm volatile("cp.async.wait_group %0;\n" :: "n"(N));
}
__device__ __forceinline__ void bar_pair(int id) {
    asm volatile("bar.sync %0, 64;" :: "r"(id) : "memory");
}
__device__ __forceinline__ void ldsm4(uint32_t* r, uint32_t a) {
    asm volatile("ldmatrix.sync.aligned.m8n8.x4.shared.b16 {%0,%1,%2,%3}, [%4];"
                 : "=r"(r[0]), "=r"(r[1]), "=r"(r[2]), "=r"(r[3]) : "r"(a));
}
__device__ __forceinline__ void ldsm2(uint32_t* r, uint32_t a) {
    asm volatile("ldmatrix.sync.aligned.m8n8.x2.shared.b16 {%0,%1}, [%2];"
                 : "=r"(r[0]), "=r"(r[1]) : "r"(a));
}
__device__ __forceinline__ void mma16816(float* c, const uint32_t* a, const uint32_t* b) {
    asm volatile(
        "mma.sync.aligned.m16n8k16.row.col.f32.f16.f16.f32 "
        "{%0,%1,%2,%3},{%4,%5,%6,%7},{%8,%9},{%0,%1,%2,%3};"
        : "+f"(c[0]), "+f"(c[1]), "+f"(c[2]), "+f"(c[3])
        : "r"(a[0]), "r"(a[1]), "r"(a[2]), "r"(a[3]), "r"(b[0]), "r"(b[1]));
}

// --------- prep B: normalize emb -> g_enT + g_Bh, norms, zero counters -----
__global__ void vq_prepB(const float* __restrict__ emb,
                         float* __restrict__ out, long long out_size) {
    int k = blockIdx.x, d = threadIdx.x;
    float v = emb[(size_t)k * DIM + d];
    float s = v * v;
    #pragma unroll
    for (int o = 16; o; o >>= 1) s += __shfl_xor_sync(0xFFFFFFFFu, s, o);
    __shared__ float ws[8]; __shared__ float rs_sh;
    if ((d & 31) == 0) ws[d >> 5] = s;
    __syncthreads();
    if (d == 0) {
        float t = 0.f;
        #pragma unroll
        for (int i = 0; i < 8; i++) t += ws[i];
        float nrm = sqrtf(t);
        rs_sh = 1.0f / fmaxf(nrm, 1e-12f);
        g_elen[k] = nrm;
        g_e2[k] = t;
        if (k == 0) {
            g_rn = 0;
            if (out_size > (long long)QN) out[QN] = 0.0f;
        }
    }
    __syncthreads();
    float en = v * rs_sh;
    g_enT[(size_t)d * K_CODES + k] = en;
    g_Bh[(size_t)k * DIM + d] = __float2half_rn(en);
}

// --------- main: pair-synchronized fp16 mma.sync GEMM + argmax + epilogue ---
__global__ void __launch_bounds__(NTHR, 2) vq_main_kernel(
    const float* __restrict__ x, const float* __restrict__ emb,
    float* __restrict__ out, long long out_size)
{
    extern __shared__ char smem[];
    const uint32_t sb = (uint32_t)__cvta_generic_to_shared(smem);
    const uint32_t sbB = sb + A_BYTES;
    const int tid  = threadIdx.x;
    const int lane = tid & 31;
    const int wid  = tid >> 5;
    const int wm   = wid & 1;
    const int wn   = wid >> 1;
    const int n0 = blockIdx.x * TM;
    const int b  = n0 >> 12;
    const int tl = n0 & 4095;

    float* xn4 = (float*)(smem + XTRA);          // [4][64]
    float* xn2 = (float*)(smem + XTRA + 1024);   // [64] (norm^2)

    // Pair (wn) owns B rows [wn*16, wn*16+16); each warp loads its 8-row half.
    auto loadB = [&](int nc) {
        const __half* Bsrc = g_Bh + (size_t)(nc * NCODE + wn * 16 + wm * 8) * DIM;
        uint32_t stg = sbB + (uint32_t)((nc & 1) * B_BYTES + (wn * 16 + wm * 8) * RS);
        #pragma unroll
        for (int i = 0; i < 8; i++)
            cp16(stg + (uint32_t)(i * RS + lane * 16), Bsrc + (size_t)i * DIM + lane * 8);
        cp_commit();
    };
    loadB(0); loadB(1);

    // ---- fused prep A: load x tile, fp16 convert into smem, row norms ----
    {
        const int r = tid & 63;
        float ss = 0.f;
        #pragma unroll 8
        for (int i = 0; i < 64; i++) {
            int d = i * 4 + (tid >> 6);
            float v = x[((size_t)b * DIM + d) * T_LEN + tl + r];
            ss = fmaf(v, v, ss);
            *(__half*)(smem + r * RS + d * 2) = __float2half_rn(v);
        }
        xn4[(tid >> 6) * 64 + r] = ss;
    }
    __syncthreads();                              // A tile + xn4 visible CTA-wide
    if (tid < TM)
        xn2[tid] = xn4[tid] + xn4[64 + tid] + xn4[128 + tid] + xn4[192 + tid];

    float rm1[4], rm2[4];
    int   ri1[4];
    #pragma unroll
    for (int i = 0; i < 4; i++) { rm1[i] = -FLT_MAX; rm2[i] = -FLT_MAX; ri1[i] = 0; }

    const int barid = 1 + wn;

    #pragma unroll 1
    for (int nc = 0; nc < NCH; nc++) {
        if (nc < NCH - 2) cp_waitg<1>(); else cp_waitg<0>();
        bar_pair(barid);                          // pair slice for chunk nc resident

        float acc[2][2][4];
        #pragma unroll
        for (int mt = 0; mt < 2; mt++)
            #pragma unroll
            for (int nt = 0; nt < 2; nt++)
                #pragma unroll
                for (int c = 0; c < 4; c++) acc[mt][nt][c] = 0.f;

        const uint32_t stgB = sbB + (uint32_t)(nc & 1) * B_BYTES;
        #pragma unroll 4
        for (int ks = 0; ks < 16; ks++) {
            uint32_t af[2][4], bf[2][2];
            #pragma unroll
            for (int mt = 0; mt < 2; mt++) {
                int row = wm * 32 + mt * 16 + (lane & 15);
                ldsm4(af[mt], sb + (uint32_t)(row * RS + ks * 32 + (lane >> 4) * 16));
            }
            #pragma unroll
            for (int nt = 0; nt < 2; nt++) {
                int rb = wn * 16 + nt * 8 + (lane & 7);
                ldsm2(bf[nt], stgB + (uint32_t)(rb * RS + ks * 32 + ((lane >> 3) & 1) * 16));
            }
            #pragma unroll
            for (int mt = 0; mt < 2; mt++)
                #pragma unroll
                for (int nt = 0; nt < 2; nt++)
                    mma16816(acc[mt][nt], af[mt], bf[nt]);
        }

        {
            int cb = nc * NCODE + wn * 16 + 2 * (lane & 3);
            #pragma unroll
            for (int mt = 0; mt < 2; mt++)
                #pragma unroll
                for (int nt = 0; nt < 2; nt++) {
                    int col = cb + nt * 8;
                    #pragma unroll
                    for (int c = 0; c < 4; c++) {
                        int slot = mt * 2 + (c >> 1);
                        int ci = col + (c & 1);
                        float v = acc[mt][nt][c];
                        if (v > rm1[slot]) { rm2[slot] = rm1[slot]; rm1[slot] = v; ri1[slot] = ci; }
                        else if (v > rm2[slot]) rm2[slot] = v;
                    }
                }
        }
        bar_pair(barid);                          // pair done reading stage nc&1
        if (nc + 2 < NCH) loadB(nc + 2);
    }
    __syncthreads();

    // ---- cross-partition top-2 reduce (reuse A region as scratch) ----
    float* redm1 = (float*)smem;                 // [64][16]
    int*   redix = (int*)(smem + 4096);          // [64][16]
    float* redm2 = (float*)(smem + 8192);        // [64][16]
    const int p = wn * 4 + (lane & 3);
    #pragma unroll
    for (int slot = 0; slot < 4; slot++) {
        int row = wm * 32 + (slot >> 1) * 16 + (slot & 1) * 8 + (lane >> 2);
        redm1[row * 16 + p] = rm1[slot];
        redix[row * 16 + p] = ri1[slot];
        redm2[row * 16 + p] = rm2[slot];
    }
    __syncthreads();

    int*   idx_s = (int*)(smem + 12288);         // [64]
    float* bestv = (float*)(smem + 12544);       // [64]
    int*   flg   = (int*)(smem + 12800);         // [64]

    if (tid < TM) {
        float g1 = -FLT_MAX, g2 = -FLT_MAX; int gi = 0;
        #pragma unroll 1
        for (int j = 0; j < 16; j++) {
            float m1 = redm1[tid * 16 + j];
            float m2 = redm2[tid * 16 + j];
            int   ix = redix[tid * 16 + j];
            if (m1 > g1) { g2 = fmaxf(fmaxf(g1, m2), g2); g1 = m1; gi = ix; }
            else         { g2 = fmaxf(g2, m1); }
        }
        idx_s[tid] = gi;
        bestv[tid] = g1;
        int f = (g1 - g2 < 2e-4f * sqrtf(xn2[tid])) ? 1 : 0;  // fp16-dot 10+ sigma
        flg[tid] = f;
        if (f) {
            int q = atomicAdd(&g_rn, 1);
            g_rlist[q] = n0 + tid;
        }
    }
    __syncthreads();

    if (tid < TM && !flg[tid] && out_size >= (long long)(QN + 1 + N_ROWS))
        out[QN + 1 + n0 + tid] = (float)idx_s[tid];

    // ---- loss from norms (per-row, non-flagged) ----
    if (tid < TM) {
        float lr = 0.f;
        if (!flg[tid]) {
            int gi = idx_s[tid];
            lr = xn2[tid] - 2.0f * g_elen[gi] * bestv[tid] + g_e2[gi];
        }
        redm1[tid] = lr;
    }
    __syncthreads();
    if (tid == 0 && out_size > (long long)QN) {
        float t = 0.f;
        #pragma unroll 1
        for (int j = 0; j < TM; j++) t += redm1[j];
        atomicAdd(out + QN, t * (1.25f / 16777216.0f));
    }

    // ---- gather + quantized write (non-flagged rows) ----
    const int r  = tid & 63;
    const int dq = tid >> 6;
    if (!flg[r]) {
        const int myidx = idx_s[r];
        const float4* erow4 = (const float4*)(emb + (size_t)myidx * DIM + dq * 64);
        float* ob = out + ((size_t)b * DIM + dq * 64) * T_LEN + tl + r;
        #pragma unroll 4
        for (int dj = 0; dj < 16; ++dj) {
            float4 e4 = erow4[dj];
            int d = dj * 4;
            ob[(size_t)(d + 0) * T_LEN] = e4.x;
            ob[(size_t)(d + 1) * T_LEN] = e4.y;
            ob[(size_t)(d + 2) * T_LEN] = e4.z;
            ob[(size_t)(d + 3) * T_LEN] = e4.w;
        }
    }
}

// --------- rescue: exact fp32 argmax + outputs for flagged rows -------------
__global__ void __launch_bounds__(RTHR, 2) vq_rescue(
    const float* __restrict__ x, const float* __restrict__ emb,
    float* __restrict__ out, long long out_size)
{
    __shared__ float xs8[8 * 256];
    __shared__ float xn8[8];
    __shared__ float rwv[8 * 8];
    __shared__ int   rwi[8 * 8];
    __shared__ int   bsel[8];
    const int tid = threadIdx.x, lane = tid & 31, wid = tid >> 5;
    const int total = g_rn;

    #pragma unroll 1
    for (int base = blockIdx.x * 8; base < total; base += gridDim.x * 8) {
        const int nb = min(8, total - base);
        #pragma unroll
        for (int i = 0; i < 8; i++) {
            int lin = i * RTHR + tid;
            int r = lin >> 8, d = lin & 255;
            int nn = g_rlist[base + (r < nb ? r : 0)];
            xs8[r * 256 + d] = x[((size_t)(nn >> 12) * DIM + d) * T_LEN + (nn & 4095)];
        }
        __syncthreads();
        {
            float s = 0.f;
            #pragma unroll
            for (int j = 0; j < 8; j++) {
                float v = xs8[wid * 256 + lane + 32 * j];
                s = fmaf(v, v, s);
            }
            #pragma unroll
            for (int o = 16; o; o >>= 1) s += __shfl_xor_sync(0xFFFFFFFFu, s, o);
            if (lane == 0) xn8[wid] = s;
        }
        float a0[8], a1[8], a2[8], a3[8];
        #pragma unroll
        for (int r = 0; r < 8; r++) { a0[r] = 0.f; a1[r] = 0.f; a2[r] = 0.f; a3[r] = 0.f; }
        #pragma unroll 4
        for (int d = 0; d < 256; d++) {
            const float* ed = g_enT + d * K_CODES + tid;
            float e0 = ed[0], e1 = ed[256], e2v = ed[512], e3 = ed[768];
            #pragma unroll
            for (int r = 0; r < 8; r++) {
                float xv = xs8[r * 256 + d];
                a0[r] = fmaf(xv, e0, a0[r]);
                a1[r] = fmaf(xv, e1, a1[r]);
                a2[r] = fmaf(xv, e2v, a2[r]);
                a3[r] = fmaf(xv, e3, a3[r]);
            }
        }
        #pragma unroll 1
        for (int r = 0; r < nb; r++) {
            float bv = a0[r]; int bi = tid;
            if (a1[r] > bv) { bv = a1[r]; bi = tid + 256; }
            if (a2[r] > bv) { bv = a2[r]; bi = tid + 512; }
            if (a3[r] > bv) { bv = a3[r]; bi = tid + 768; }
            #pragma unroll
            for (int o = 16; o; o >>= 1) {
                float ov = __shfl_xor_sync(0xFFFFFFFFu, bv, o);
                int   oi = __shfl_xor_sync(0xFFFFFFFFu, bi, o);
                if (ov > bv || (ov == bv && oi < bi)) { bv = ov; bi = oi; }
            }
            if (lane == 0) { rwv[r * 8 + wid] = bv; rwi[r * 8 + wid] = bi; }
        }
        __syncthreads();
        if (tid < nb) {
            float best = rwv[tid * 8]; int besti = rwi[tid * 8];
            #pragma unroll
            for (int j = 1; j < 8; j++) {
                float v = rwv[tid * 8 + j]; int ix = rwi[tid * 8 + j];
                if (v > best || (v == best && ix < besti)) { best = v; besti = ix; }
            }
            bsel[tid] = besti;
            int nn = g_rlist[base + tid];
            if (out_size >= (long long)(QN + 1 + N_ROWS))
                out[QN + 1 + nn] = (float)besti;
            if (out_size > (long long)QN)
                atomicAdd(out + QN,
                    (xn8[tid] - 2.0f * g_elen[besti] * best + g_e2[besti]) * (1.25f / 16777216.0f));
        }
        __syncthreads();
        #pragma unroll 1
        for (int r = 0; r < nb; r++) {
            int nn = g_rlist[base + r];
            int bi = bsel[r];
            out[((size_t)(nn >> 12) * DIM + tid) * T_LEN + (nn & 4095)] =
                emb[(size_t)bi * DIM + tid];
        }
        __syncthreads();
    }
}

// ---------------------------------------------------------------------------
extern "C" void kernel_launch(void* const* d_in, const int* in_sizes, int n_in,
                              void* d_out, int out_size) {
    const float* x   = (const float*)d_in[0];
    const float* emb = (const float*)d_in[1];
    if (n_in >= 2 && in_sizes[0] == K_CODES * DIM && in_sizes[1] == (int)QN) {
        const float* t = x; x = emb; emb = t;
    }
    float* out = (float*)d_out;

    cudaFuncSetAttribute(vq_main_kernel, cudaFuncAttributeMaxDynamicSharedMemorySize, SMEM_M);

    vq_prepB<<<K_CODES, 256>>>(emb, out, (long long)out_size);
    vq_main_kernel<<<N_ROWS / TM, NTHR, SMEM_M>>>(x, emb, out, (long long)out_size);
    vq_rescue<<<RGRID, RTHR>>>(x, emb, out, (long long)out_size);
}